// round 8
// baseline (speedup 1.0000x reference)
#include <cuda_runtime.h>
#include <cstdint>

// Dims: N=32, K=32, T=128, H=768
#define NN 32
#define KK 32
#define TT 128
#define HH 768
#define H2 1536

// Output layout (float32 concat)
#define OFF_SCORE 0
#define OFF_ENC   1024
#define OFF_MASK  (1024 + 3145728)
#define OFF_USE   (OFF_MASK + 4096)
#define OFF_IDX   (OFF_USE + 24576)

#define GRID_BLOCKS 296            // 2 per SM on 148 SMs (<=304 on GB300's 152)
#define THREADS     256
#define TOTAL_THREADS (GRID_BLOCKS * THREADS)   // 75776
#define TOTAL_WARPS   (GRID_BLOCKS * 8)         // 2368

// Scratch
__device__ float g_cqk[NN * HH];   // cqk_pro [n][g] (bias folded)
__device__ float g_v[NN * HH];     // v [n][h]
__device__ float g_c[NN];          // b_k . cqk_pro[n]

// Monotonic grid barriers (never reset; release target derived from ticket,
// so graph replays — which serialize — each form their own generation).
__device__ unsigned g_bar0, g_bar1;

__device__ __forceinline__ void grid_barrier(unsigned* bar) {
    __syncthreads();
    if (threadIdx.x == 0) {
        __threadfence();                       // release all prior writes
        unsigned t = atomicAdd(bar, 1u);
        unsigned target = (t / GRID_BLOCKS + 1u) * GRID_BLOCKS;
        volatile unsigned* p = bar;
        while (*p < target) __nanosleep(32);
        __threadfence();                       // acquire
    }
    __syncthreads();
}

// ---------------------------------------------------------------------------
// Single persistent kernel:
//  phase 0: kA GEMV (8-way n-blocked) | L2 prefetch (W_k, p1) | gather
//  barrier
//  phase 1: v[n,h] = sum_g cqk[n,g] W_k[g,h]   and   c[n] = b_k . cqk[n,:]
//  barrier
//  phase 2: score[n,k] = p1[n,k,:].v[n,:] + c[n], masked
// ---------------------------------------------------------------------------
__global__ void __launch_bounds__(THREADS, 2) k_all(
    const float* __restrict__ ctx,      // (N,3,H)
    const float* __restrict__ tracked,  // (N,H)
    const float* __restrict__ W_cqk,    // (H,2H)
    const float* __restrict__ b_cqk,    // (H,)
    const float* __restrict__ p0,       // (N,K,T,H)
    const float* __restrict__ p1,       // (N,K,H)
    const int*   __restrict__ pmask,    // (N,K,T) bool-as-int32
    const int*   __restrict__ label,    // (N,)
    const int*   __restrict__ ptok,     // (N,K,T)
    const int*   __restrict__ ck_mask,  // (N,K) bool-as-int32
    const float* __restrict__ W_k,      // (H,H)
    const float* __restrict__ b_k,      // (H,)
    float* __restrict__ out)
{
    __shared__ float sc[HH * 9];                // phase1: cqk [g][nn], 27.6 KB
    __shared__ float red[2 * 4 * 32 * 9];       // phase1: per-half partials
    __shared__ float cred[32 * 9];              // phase1: c partials

    int tid  = threadIdx.x;
    int lane = tid & 31;

    // ======================= PHASE 0 =======================
    // kA: job = (g, ngroup of 8 n); lanes split W row (coalesced LDG.128).
    {
        int gwarp = blockIdx.x * 8 + (tid >> 5);
        for (int job = gwarp; job < 4 * HH; job += TOTAL_WARPS) {
            int g  = job >> 2;
            int n0 = (job & 3) * 8;
            const float4* W4 = reinterpret_cast<const float4*>(W_cqk + (size_t)g * H2);

            float acc[8];
#pragma unroll
            for (int nn = 0; nn < 8; ++nn) acc[nn] = 0.f;

#pragma unroll
            for (int i = 0; i < 6; ++i) {
                int j = lane + 32 * i;          // 0..191
                float4 w  = W4[j];
                float4 w2 = W4[192 + j];
#pragma unroll
                for (int nn = 0; nn < 8; ++nn) {
                    int n = n0 + nn;
                    float4 x  = reinterpret_cast<const float4*>(
                        ctx + ((size_t)n * 3 + 2) * HH)[j];
                    float4 x2 = reinterpret_cast<const float4*>(
                        tracked + (size_t)n * HH)[j];
                    float s = acc[nn];
                    s = fmaf(w.x,  x.x,  s); s = fmaf(w.y,  x.y,  s);
                    s = fmaf(w.z,  x.z,  s); s = fmaf(w.w,  x.w,  s);
                    s = fmaf(w2.x, x2.x, s); s = fmaf(w2.y, x2.y, s);
                    s = fmaf(w2.z, x2.z, s); s = fmaf(w2.w, x2.w, s);
                    acc[nn] = s;
                }
            }
            float bg = __ldg(b_cqk + g);
#pragma unroll
            for (int nn = 0; nn < 8; ++nn) {
                float s = acc[nn];
#pragma unroll
                for (int o = 16; o > 0; o >>= 1) s += __shfl_down_sync(0xffffffffu, s, o);
                if (lane == 0) g_cqk[(size_t)(n0 + nn) * HH + g] = s + bg;
            }
        }
    }

    // L2 prefetch: W_k (2.25 MB, phase 1) + p1 (3 MB, phase 2)
    {
        int gt = blockIdx.x * THREADS + tid;
        const char* b2 = (const char*)W_k;
        for (int i = gt; i < 18432; i += TOTAL_THREADS)
            asm volatile("prefetch.global.L2 [%0];" :: "l"(b2 + (size_t)i * 128));
        const char* b1 = (const char*)p1;
        for (int i = gt; i < 24576; i += TOTAL_THREADS)
            asm volatile("prefetch.global.L2 [%0];" :: "l"(b1 + (size_t)i * 128));
    }

    // gather (grid-stride)
    {
        const int ENC_F4 = NN * TT * HH / 4;    // 786432
        const int USE_F4 = NN * HH / 4;         // 6144
        const int MT     = NN * TT;             // 4096
        const int TOTAL  = ENC_F4 + USE_F4 + 2 * MT;

        for (int idx0 = blockIdx.x * THREADS + tid; idx0 < TOTAL; idx0 += TOTAL_THREADS) {
            int idx = idx0;
            if (idx < ENC_F4) {
                int per_n = TT * HH / 4;        // 24576
                int n = idx / per_n;
                int r = idx - n * per_n;
                int lab = __ldg(label + n);
                const float4* src = reinterpret_cast<const float4*>(
                    p0 + ((size_t)(n * KK + lab)) * TT * HH);
                float4* dst = reinterpret_cast<float4*>(out + OFF_ENC + (size_t)n * TT * HH);
                dst[r] = src[r];
                continue;
            }
            idx -= ENC_F4;
            if (idx < USE_F4) {
                int per_n = HH / 4;             // 192
                int n = idx / per_n;
                int r = idx - n * per_n;
                int lab = __ldg(label + n);
                const float4* src = reinterpret_cast<const float4*>(
                    p1 + ((size_t)(n * KK + lab)) * HH);
                float4* dst = reinterpret_cast<float4*>(out + OFF_USE + (size_t)n * HH);
                dst[r] = src[r];
                continue;
            }
            idx -= USE_F4;
            if (idx < MT) {
                int n = idx / TT;
                int t = idx - n * TT;
                int lab = __ldg(label + n);
                out[OFF_MASK + idx] = (pmask[((size_t)(n * KK + lab)) * TT + t] != 0) ? 1.0f : 0.0f;
                continue;
            }
            idx -= MT;
            {
                int n = idx / TT;
                int t = idx - n * TT;
                int lab = __ldg(label + n);
                out[OFF_IDX + idx] = (float)ptok[((size_t)(n * KK + lab)) * TT + t];
            }
        }
    }

    grid_barrier(&g_bar0);

    // ======================= PHASE 1 =======================
    // 48 blocks: each handles one ngrp (8 n) and TWO h-tiles of 32 (one per
    // 128-thread half). sc shared across halves. Block 48 computes c[n].
    if (blockIdx.x < 48) {
        int ngrp = blockIdx.x / 12;
        int htp  = blockIdx.x % 12;
        int n0   = ngrp * 8;

        for (int s = tid; s < 8 * HH; s += THREADS) {
            int nn = s / HH;
            int g  = s - nn * HH;
            sc[g * 9 + nn] = g_cqk[(size_t)(n0 + nn) * HH + g];
        }
        __syncthreads();

        int half = tid >> 7;                    // 0/1
        int tidh = tid & 127;
        int hl   = tidh & 31;
        int gsub = tidh >> 5;                   // 0..3
        int h0   = (htp * 2 + half) * 32;

        float acc[8];
#pragma unroll
        for (int nn = 0; nn < 8; ++nn) acc[nn] = 0.f;

        int gbase = gsub * 192;
#pragma unroll 8
        for (int i = 0; i < 192; ++i) {
            int g = gbase + i;
            float wv = __ldg(W_k + (size_t)g * HH + h0 + hl);
#pragma unroll
            for (int nn = 0; nn < 8; ++nn)
                acc[nn] = fmaf(wv, sc[g * 9 + nn], acc[nn]);
        }

        float* redh = red + half * (4 * 32 * 9);
#pragma unroll
        for (int nn = 0; nn < 8; ++nn) redh[(gsub * 32 + hl) * 9 + nn] = acc[nn];
        __syncthreads();

        for (int o = tidh; o < 256; o += 128) {
            int ohl = o >> 3;
            int onn = o & 7;
            float s = redh[(0 * 32 + ohl) * 9 + onn] + redh[(1 * 32 + ohl) * 9 + onn]
                    + redh[(2 * 32 + ohl) * 9 + onn] + redh[(3 * 32 + ohl) * 9 + onn];
            g_v[(size_t)(n0 + onn) * HH + h0 + ohl] = s;
        }
    } else if (blockIdx.x == 48) {
        // c[n] = b_k . cqk[n,:]; 256 threads: n = tid>>3, 8 g-segments of 96
        int n = tid >> 3;
        int q = tid & 7;
        float s = 0.f;
        for (int i = 0; i < 96; ++i) {
            int g = q * 96 + i;
            s = fmaf(__ldg(b_k + g), g_cqk[(size_t)n * HH + g], s);
        }
        cred[n * 9 + q] = s;
        __syncthreads();
        if (tid < 32) {
            float t = 0.f;
#pragma unroll
            for (int j = 0; j < 8; ++j) t += cred[tid * 9 + j];
            g_c[tid] = t;
        }
    }

    grid_barrier(&g_bar1);

    // ======================= PHASE 2 =======================
    // score: warp per (n,k); p1 L2-resident.
    {
        int wjob = blockIdx.x * 8 + (tid >> 5);
        if (wjob < NN * KK) {
            int n = wjob / KK;
            int k = wjob - n * KK;

            const float4* p4 = reinterpret_cast<const float4*>(p1 + ((size_t)n * KK + k) * HH);
            const float4* v4 = reinterpret_cast<const float4*>(g_v + (size_t)n * HH);

            float s = 0.f;
#pragma unroll
            for (int j = lane; j < 192; j += 32) {
                float4 a = p4[j];
                float4 b = v4[j];
                s = fmaf(a.x, b.x, s); s = fmaf(a.y, b.y, s);
                s = fmaf(a.z, b.z, s); s = fmaf(a.w, b.w, s);
            }
#pragma unroll
            for (int o = 16; o > 0; o >>= 1) s += __shfl_down_sync(0xffffffffu, s, o);
            if (lane == 0) {
                s += g_c[n];
                if (ck_mask[n * KK + k] == 0) s = -1e20f;
                out[OFF_SCORE + n * KK + k] = s;
            }
        }
    }
}

extern "C" void kernel_launch(void* const* d_in, const int* in_sizes, int n_in,
                              void* d_out, int out_size) {
    const float* ctx     = (const float*)d_in[0];
    const float* tracked = (const float*)d_in[1];
    const float* p0      = (const float*)d_in[2];
    const float* p1      = (const float*)d_in[3];
    const int*   pmask   = (const int*)d_in[4];
    const int*   ckmask  = (const int*)d_in[5];
    const int*   label   = (const int*)d_in[6];
    const int*   ptok    = (const int*)d_in[7];
    const float* W_cqk   = (const float*)d_in[8];
    const float* b_cqk   = (const float*)d_in[9];
    const float* W_k     = (const float*)d_in[10];
    const float* b_k     = (const float*)d_in[11];
    float* out = (float*)d_out;

    k_all<<<GRID_BLOCKS, THREADS>>>(ctx, tracked, W_cqk, b_cqk,
                                    p0, p1, pmask, label, ptok, ckmask,
                                    W_k, b_k, out);
}

// round 9
// speedup vs baseline: 1.0683x; 1.0683x over previous
#include <cuda_runtime.h>
#include <cstdint>

// Dims: N=32, K=32, T=128, H=768
#define NN 32
#define KK 32
#define TT 128
#define HH 768
#define H2 1536

// Output layout (float32 concat)
#define OFF_SCORE 0
#define OFF_ENC   1024
#define OFF_MASK  (1024 + 3145728)
#define OFF_USE   (OFF_MASK + 4096)
#define OFF_IDX   (OFF_USE + 24576)

// Scratch
__device__ float g_cqk[NN * HH];   // cqk_pro [n][g] (bias folded)
__device__ float g_v[NN * HH];     // v [n][h]
__device__ float g_c[NN];          // b_k . cqk_pro[n]

// K1 block ranges
#define KA_BLOCKS  384             // kA: 3072 warps = (g 768) x (ngrp 4)
#define PF_BLOCKS  16
#define ENC_BLOCKS 384             // enc copy: 3072 warp-jobs x 256 f4 (MLP 8)
#define USE_BLOCKS 6               // use copy: 1536 threads x 4 f4
#define MSK_BLOCKS 32              // mask+idx: 8192 scalar items
#define PF_BASE   KA_BLOCKS
#define ENC_BASE  (PF_BASE + PF_BLOCKS)
#define USE_BASE  (ENC_BASE + ENC_BLOCKS)
#define MSK_BASE  (USE_BASE + USE_BLOCKS)
#define K1_BLOCKS (MSK_BASE + MSK_BLOCKS)     // 822

// ---------------------------------------------------------------------------
// K1: fused [kA GEMV | L2 prefetch | gather(MLP-8)]
// ---------------------------------------------------------------------------
__global__ void __launch_bounds__(256) k1_fused(
    const float* __restrict__ ctx,      // (N,3,H)
    const float* __restrict__ tracked,  // (N,H)
    const float* __restrict__ W_cqk,    // (H,2H)
    const float* __restrict__ b_cqk,    // (H,)
    const float* __restrict__ p0,       // (N,K,T,H)
    const float* __restrict__ p1,       // (N,K,H)
    const int*   __restrict__ pmask,    // (N,K,T) bool-as-int32
    const int*   __restrict__ label,    // (N,)
    const int*   __restrict__ ptok,     // (N,K,T)
    const float* __restrict__ W_k,      // (H,H)
    float* __restrict__ out)
{
    int blk  = blockIdx.x;
    int tid  = threadIdx.x;
    int lane = tid & 31;

    if (blk < KA_BLOCKS) {
        // ---- kA: warp = (g, ngroup of 8 n); lanes split W row ----
        int gw = blk * 8 + (tid >> 5);          // 0..3071
        int g  = gw >> 2;
        int n0 = (gw & 3) * 8;

        const float4* W4 = reinterpret_cast<const float4*>(W_cqk + (size_t)g * H2);

        float acc[8];
#pragma unroll
        for (int nn = 0; nn < 8; ++nn) acc[nn] = 0.f;

#pragma unroll
        for (int i = 0; i < 6; ++i) {
            int j = lane + 32 * i;              // 0..191
            float4 w  = W4[j];
            float4 w2 = W4[192 + j];
#pragma unroll
            for (int nn = 0; nn < 8; ++nn) {
                int n = n0 + nn;
                float4 x  = reinterpret_cast<const float4*>(
                    ctx + ((size_t)n * 3 + 2) * HH)[j];
                float4 x2 = reinterpret_cast<const float4*>(
                    tracked + (size_t)n * HH)[j];
                float s = acc[nn];
                s = fmaf(w.x,  x.x,  s); s = fmaf(w.y,  x.y,  s);
                s = fmaf(w.z,  x.z,  s); s = fmaf(w.w,  x.w,  s);
                s = fmaf(w2.x, x2.x, s); s = fmaf(w2.y, x2.y, s);
                s = fmaf(w2.z, x2.z, s); s = fmaf(w2.w, x2.w, s);
                acc[nn] = s;
            }
        }
        float bg = __ldg(b_cqk + g);
#pragma unroll
        for (int nn = 0; nn < 8; ++nn) {
            float s = acc[nn];
#pragma unroll
            for (int o = 16; o > 0; o >>= 1) s += __shfl_down_sync(0xffffffffu, s, o);
            if (lane == 0) g_cqk[(size_t)(n0 + nn) * HH + g] = s + bg;
        }
        return;
    }

    if (blk < ENC_BASE) {
        // ---- L2 prefetch: W_k (2.25MB) + p1 (3MB) ----
        int pidx = (blk - PF_BASE) * 256 + tid;
        const char* b2 = (const char*)W_k;
        for (int i = pidx; i < 18432; i += PF_BLOCKS * 256)
            asm volatile("prefetch.global.L2 [%0];" :: "l"(b2 + (size_t)i * 128));
        const char* b1 = (const char*)p1;
        for (int i = pidx; i < 24576; i += PF_BLOCKS * 256)
            asm volatile("prefetch.global.L2 [%0];" :: "l"(b1 + (size_t)i * 128));
        return;
    }

    if (blk < USE_BASE) {
        // ---- enc copy: warp-job = 256 contiguous f4 within one n (MLP 8) ----
        int wjob = (blk - ENC_BASE) * 8 + (tid >> 5);   // 0..3071
        int n  = wjob / 96;                             // 96 jobs per n
        int r0 = (wjob - n * 96) * 256;
        int lab = __ldg(label + n);
        const float4* src = reinterpret_cast<const float4*>(
            p0 + ((size_t)(n * KK + lab)) * TT * HH);
        float4* dst = reinterpret_cast<float4*>(out + OFF_ENC + (size_t)n * TT * HH);

        float4 v[8];
#pragma unroll
        for (int u = 0; u < 8; ++u) v[u] = src[r0 + u * 32 + lane];
#pragma unroll
        for (int u = 0; u < 8; ++u) dst[r0 + u * 32 + lane] = v[u];
        return;
    }

    if (blk < MSK_BASE) {
        // ---- use copy: 6144 f4, thread handles 4 (MLP 4) ----
        int t = (blk - USE_BASE) * 256 + tid;           // 0..1535
        float4 v[4];
        int idx[4];
#pragma unroll
        for (int u = 0; u < 4; ++u) {
            int i = t + u * 1536;                       // 0..6143
            int n = i / 192;
            int r = i - n * 192;
            int lab = __ldg(label + n);
            idx[u] = n * 192 + r;
            v[u] = reinterpret_cast<const float4*>(
                p1 + ((size_t)(n * KK + lab)) * HH)[r];
        }
#pragma unroll
        for (int u = 0; u < 4; ++u)
            reinterpret_cast<float4*>(out + OFF_USE)[idx[u]] = v[u];
        return;
    }

    // ---- mask + idx: 8192 scalar items ----
    {
        int i = (blk - MSK_BASE) * 256 + tid;           // 0..8191
        const int MT = NN * TT;                         // 4096
        if (i < MT) {
            int n = i / TT;
            int t = i - n * TT;
            int lab = __ldg(label + n);
            out[OFF_MASK + i] = (pmask[((size_t)(n * KK + lab)) * TT + t] != 0) ? 1.0f : 0.0f;
        } else {
            int j = i - MT;
            int n = j / TT;
            int t = j - n * TT;
            int lab = __ldg(label + n);
            out[OFF_IDX + j] = (float)ptok[((size_t)(n * KK + lab)) * TT + t];
        }
    }
}

// ---------------------------------------------------------------------------
// K2: v[n,h] = sum_g cqk[n,g] * W_k[g,h]  — float4 W loads, MLP ~24
//   96 compute blocks x 256 thr: blk = (ngrp 0..3) x (ht 0..23, 32 h each).
//   Thread: gsub = tid>>3 (32-way g split, 24 g each), hf4 = tid&7 (4 h).
//   Block 96: c[n] = b_k . cqk[n,:].
// ---------------------------------------------------------------------------
__global__ void __launch_bounds__(256) k2_v(
    const float* __restrict__ W_k,   // (H,H)
    const float* __restrict__ b_k)   // (H,)
{
    __shared__ float sc[HH * 9];                 // [g][nn] stride 9, 27.6 KB
    __shared__ float4 red[32 * 64];              // [gsub][hf4*8+nn], 32 KB

    int blk = blockIdx.x;
    int tid = threadIdx.x;

    if (blk < 96) {
        int ngrp = blk / 24;
        int ht   = blk - ngrp * 24;
        int n0   = ngrp * 8;
        int h0   = ht * 32;
        int gsub = tid >> 3;                     // 0..31
        int hf4  = tid & 7;                      // 0..7
        int h    = h0 + hf4 * 4;

        for (int s = tid; s < 8 * HH; s += 256) {
            int nn = s / HH;
            int g  = s - nn * HH;
            sc[g * 9 + nn] = g_cqk[(size_t)(n0 + nn) * HH + g];
        }
        __syncthreads();

        float4 acc[8];
#pragma unroll
        for (int nn = 0; nn < 8; ++nn) acc[nn] = make_float4(0.f, 0.f, 0.f, 0.f);

        int g0 = gsub * 24;
#pragma unroll 6
        for (int i = 0; i < 24; ++i) {
            int g = g0 + i;
            float4 wv = __ldg(reinterpret_cast<const float4*>(
                W_k + (size_t)g * HH + h));
#pragma unroll
            for (int nn = 0; nn < 8; ++nn) {
                float x = sc[g * 9 + nn];
                acc[nn].x = fmaf(wv.x, x, acc[nn].x);
                acc[nn].y = fmaf(wv.y, x, acc[nn].y);
                acc[nn].z = fmaf(wv.z, x, acc[nn].z);
                acc[nn].w = fmaf(wv.w, x, acc[nn].w);
            }
        }

#pragma unroll
        for (int nn = 0; nn < 8; ++nn) red[gsub * 64 + hf4 * 8 + nn] = acc[nn];
        __syncthreads();

        // 64 outputs (hf4 x nn), each summed over 32 gsub
        if (tid < 64) {
            int ohf4 = tid >> 3;
            int onn  = tid & 7;
            float4 s = make_float4(0.f, 0.f, 0.f, 0.f);
#pragma unroll
            for (int gs = 0; gs < 32; ++gs) {
                float4 p = red[gs * 64 + tid];
                s.x += p.x; s.y += p.y; s.z += p.z; s.w += p.w;
            }
            *reinterpret_cast<float4*>(
                g_v + (size_t)(n0 + onn) * HH + h0 + ohf4 * 4) = s;
        }
        return;
    }

    // ---- c[n] = b_k . cqk[n,:]  (block 96) ----
    __shared__ float cred[32 * 9];
    int n = tid >> 3;
    int q = tid & 7;
    float s = 0.f;
    for (int i = 0; i < 96; ++i) {
        int g = q * 96 + i;
        s = fmaf(__ldg(b_k + g), g_cqk[(size_t)n * HH + g], s);
    }
    cred[n * 9 + q] = s;
    __syncthreads();
    if (tid < 32) {
        float t = 0.f;
#pragma unroll
        for (int j = 0; j < 8; ++j) t += cred[tid * 9 + j];
        g_c[tid] = t;
    }
}

// ---------------------------------------------------------------------------
// K3: score[n,k] = p1[n,k,:].v[n,:] + c[n], masked. Warp per (n,k).
// p1 + v L2-resident.
// ---------------------------------------------------------------------------
__global__ void __launch_bounds__(256) k3_score(
    const float* __restrict__ p1,        // (N,K,H)
    const int* __restrict__ ck_mask,     // (N,K) bool-as-int32
    float* __restrict__ out)
{
    int wid  = blockIdx.x * 8 + (threadIdx.x >> 5);
    int lane = threadIdx.x & 31;
    int n = wid / KK;
    int k = wid - n * KK;

    const float4* p4 = reinterpret_cast<const float4*>(p1 + ((size_t)n * KK + k) * HH);
    const float4* v4 = reinterpret_cast<const float4*>(g_v + (size_t)n * HH);

    float4 a[6], b[6];
#pragma unroll
    for (int i = 0; i < 6; ++i) {
        int j = lane + 32 * i;
        a[i] = p4[j];
        b[i] = v4[j];
    }
    float s = 0.f;
#pragma unroll
    for (int i = 0; i < 6; ++i) {
        s = fmaf(a[i].x, b[i].x, s); s = fmaf(a[i].y, b[i].y, s);
        s = fmaf(a[i].z, b[i].z, s); s = fmaf(a[i].w, b[i].w, s);
    }
#pragma unroll
    for (int o = 16; o > 0; o >>= 1) s += __shfl_down_sync(0xffffffffu, s, o);
    if (lane == 0) {
        s += g_c[n];
        if (ck_mask[n * KK + k] == 0) s = -1e20f;
        out[OFF_SCORE + n * KK + k] = s;
    }
}

extern "C" void kernel_launch(void* const* d_in, const int* in_sizes, int n_in,
                              void* d_out, int out_size) {
    const float* ctx     = (const float*)d_in[0];
    const float* tracked = (const float*)d_in[1];
    const float* p0      = (const float*)d_in[2];
    const float* p1      = (const float*)d_in[3];
    const int*   pmask   = (const int*)d_in[4];
    const int*   ckmask  = (const int*)d_in[5];
    const int*   label   = (const int*)d_in[6];
    const int*   ptok    = (const int*)d_in[7];
    const float* W_cqk   = (const float*)d_in[8];
    const float* b_cqk   = (const float*)d_in[9];
    const float* W_k     = (const float*)d_in[10];
    const float* b_k     = (const float*)d_in[11];
    float* out = (float*)d_out;

    k1_fused<<<K1_BLOCKS, 256>>>(ctx, tracked, W_cqk, b_cqk,
                                 p0, p1, pmask, label, ptok, W_k, out);
    k2_v<<<97, 256>>>(W_k, b_k);
    k3_score<<<(NN * KK) / 8, 256>>>(p1, ckmask, out);
}